// round 15
// baseline (speedup 1.0000x reference)
#include <cuda_runtime.h>

// Chamfer distance, pc1/pc2: (1, 16384, 3) fp32 -> scalar fp32.
// R15: x-bin-sorted windowed brute (packed f32x2) + exact block-amortized
//      extension pass (phaseB). No warp-per-query path. 5 launches.

#define NP     16384
#define NB     4096
#define XMIN   (-6.0f)
#define XRANGE (12.0f)
#define INVBW  (NB / XRANGE)

#define QB     256                    // queries per group
#define NGRP   (NP / QB)              // 64 groups per direction
#define TB     128                    // threads (2 packed queries each)
#define W      512                    // phaseA window margin (counts)
#define SLICES 4
#define CH     256                    // smem chunk points

__device__ float4 s_pts[2][NP];       // x-bin-sorted; w = original index bits
__device__ int    bin_start[2][NB];
__device__ int    scatter_pos[2][NB];
__device__ int    g_d[2 * NP];        // float bits of NN d2 (<= 2.0 cap)

#define FMA2(out, a, b, c) \
    asm("fma.rn.f32x2 %0, %1, %2, %3;" : "=l"(out) : "l"(a), "l"(b), "l"(c))
#define ADD2(out, a, b) \
    asm("add.rn.f32x2 %0, %1, %2;" : "=l"(out) : "l"(a), "l"(b))
#define PACK2(out, lo, hi) \
    asm("mov.b64 %0, {%1, %2};" : "=l"(out) : "f"(lo), "f"(hi))
#define UNPACK2(lo, hi, in) \
    asm("mov.b64 {%0, %1}, %2;" : "=f"(lo), "=f"(hi) : "l"(in))

__device__ __forceinline__ int xbin(float x) {
    int b = (int)((x - XMIN) * INVBW);
    return min(max(b, 0), NB - 1);
}

// Single block: smem histogram of both clouds + exclusive scan -> bin_start.
__global__ void __launch_bounds__(1024) build_kernel(
    const float* __restrict__ pc1, const float* __restrict__ pc2)
{
    __shared__ int sbin[2][NB];       // 32 KB
    __shared__ int wsum[32];
    const int tid = threadIdx.x, lane = tid & 31, wid = tid >> 5;

    for (int i = tid; i < 2 * NB; i += 1024) ((int*)sbin)[i] = 0;
    __syncthreads();
    for (int i = tid; i < 2 * NP; i += 1024) {
        int dir = i >> 14, idx = i & (NP - 1);
        const float* pc = dir ? pc2 : pc1;
        atomicAdd(&sbin[dir][xbin(pc[3 * idx])], 1);
    }
    __syncthreads();

#pragma unroll 1
    for (int dir = 0; dir < 2; dir++) {
        int base = tid * 4;
        int c0 = sbin[dir][base + 0], c1 = sbin[dir][base + 1];
        int c2 = sbin[dir][base + 2], c3 = sbin[dir][base + 3];
        int s0 = c0, s1 = s0 + c1, s2 = s1 + c2, s3 = s2 + c3;
        int tot = s3, v = tot;
#pragma unroll
        for (int o = 1; o < 32; o <<= 1) {
            int u = __shfl_up_sync(0xffffffffu, v, o);
            if (lane >= o) v += u;
        }
        if (lane == 31) wsum[wid] = v;
        __syncthreads();
        if (wid == 0) {
            int w = wsum[lane];
#pragma unroll
            for (int o = 1; o < 32; o <<= 1) {
                int u = __shfl_up_sync(0xffffffffu, w, o);
                if (lane >= o) w += u;
            }
            wsum[lane] = w;
        }
        __syncthreads();
        int warp_excl = (wid == 0) ? 0 : wsum[wid - 1];
        int ebase = warp_excl + (v - tot);
        bin_start[dir][base + 0] = ebase;
        bin_start[dir][base + 1] = ebase + s0;
        bin_start[dir][base + 2] = ebase + s1;
        bin_start[dir][base + 3] = ebase + s2;
        scatter_pos[dir][base + 0] = ebase;
        scatter_pos[dir][base + 1] = ebase + s0;
        scatter_pos[dir][base + 2] = ebase + s1;
        scatter_pos[dir][base + 3] = ebase + s2;
        __syncthreads();
    }
}

__global__ void scatter_kernel(const float* __restrict__ pc1,
                               const float* __restrict__ pc2) {
    int i = blockIdx.x * blockDim.x + threadIdx.x;
    int dir = i >> 14, idx = i & (NP - 1);
    const float* pc = dir ? pc2 : pc1;
    float x = pc[3 * idx], y = pc[3 * idx + 1], z = pc[3 * idx + 2];
    int pos = atomicAdd(&scatter_pos[dir][xbin(x)], 1);
    s_pts[dir][pos] = make_float4(x, y, z, __int_as_float(idx));
    g_d[i] = __float_as_int(2.0f);            // threshold cap = init
}

// Shared inner tile: scan [lo, hi] of R against 2 packed queries.
__device__ __forceinline__ void scan_range(
    const float4* __restrict__ R, int lo, int hi, float* sh, int tid,
    unsigned long long Qx, unsigned long long Qy, unsigned long long Qz,
    unsigned long long Qw, float& ma, float& mb)
{
    for (int base = lo; base <= hi; base += CH) {
        int n = min(CH, hi - base + 1);
        __syncthreads();
        for (int i = tid; i < n; i += TB) {
            float4 r = R[base + i];
            float yy = r.x * r.x + r.y * r.y + r.z * r.z;
            float* s = &sh[i * 8];
            s[0] = -2.0f * r.x; s[1] = -2.0f * r.x;
            s[2] = -2.0f * r.y; s[3] = -2.0f * r.y;
            s[4] = -2.0f * r.z; s[5] = -2.0f * r.z;
            s[6] = yy;          s[7] = yy;
        }
        __syncthreads();
#pragma unroll 4
        for (int j = 0; j < n; j++) {
            const ulonglong2* sp = (const ulonglong2*)&sh[j * 8];
            ulonglong2 A = sp[0];
            ulonglong2 B = sp[1];
            unsigned long long u1, u2, d;
            FMA2(u1, Qx, A.x, B.y);     // yy - 2 x0 y0
            FMA2(u2, Qy, A.y, Qw);      // xx - 2 x1 y1
            FMA2(u1, Qz, B.x, u1);
            ADD2(d, u1, u2);            // full d2, packed (qa, qb)
            float lo2, hi2;
            UNPACK2(lo2, hi2, d);
            ma = fminf(ma, lo2);
            mb = fminf(mb, hi2);
        }
    }
}

// Windowed brute: 256 consecutive sorted queries vs shared window, 4 slices.
__global__ void __launch_bounds__(TB) phaseA_kernel() {
    __shared__ float sh[CH * 8];
    __shared__ int wmn, wmx;
    const int tid   = threadIdx.x;
    const int qlo   = blockIdx.x * QB;
    const int slice = blockIdx.y;
    const int dir   = blockIdx.z;
    const float4* __restrict__ R = s_pts[dir ^ 1];

    if (tid == 0) { wmn = 0x7FFFFFFF; wmx = 0; }
    __syncthreads();

    const int qa = qlo + tid, qb = qlo + tid + TB;
    float4 pa = s_pts[dir][qa], pb = s_pts[dir][qb];
    int ca = bin_start[dir ^ 1][xbin(pa.x)];
    int cb = bin_start[dir ^ 1][xbin(pb.x)];
    atomicMin(&wmn, min(ca, cb));
    atomicMax(&wmx, max(ca, cb));
    __syncthreads();
    const int wlo = max(wmn - W, 0), whi = min(wmx + W, NP - 1);
    const int cnt = whi - wlo + 1;
    const int slo = wlo + (cnt * slice) / SLICES;
    const int shi = wlo + (cnt * (slice + 1)) / SLICES - 1;

    unsigned long long Qx, Qy, Qz, Qw;
    PACK2(Qx, pa.x, pb.x);
    PACK2(Qy, pa.y, pb.y);
    PACK2(Qz, pa.z, pb.z);
    PACK2(Qw, pa.x * pa.x + pa.y * pa.y + pa.z * pa.z,
              pb.x * pb.x + pb.y * pb.y + pb.z * pb.z);
    float ma = 2.0f, mb = 2.0f;

    scan_range(R, slo, shi, sh, tid, Qx, Qy, Qz, Qw, ma, mb);

    atomicMin(&g_d[dir * NP + __float_as_int(pa.w)], __float_as_int(ma));
    atomicMin(&g_d[dir * NP + __float_as_int(pb.w)], __float_as_int(mb));
}

// Exact completion: per-group needed range from sqrt(best); scan only the
// extension beyond phaseA's window. Block-amortized, no warp-per-query path.
__global__ void __launch_bounds__(TB) phaseB_kernel() {
    __shared__ float sh[CH * 8];
    __shared__ int wmn, wmx, nlo, nhi;
    const int tid = threadIdx.x;
    const int qlo = blockIdx.x * QB;
    const int dir = blockIdx.y;
    const float4* __restrict__ R = s_pts[dir ^ 1];
    const int* __restrict__ BS = bin_start[dir ^ 1];

    if (tid == 0) { wmn = 0x7FFFFFFF; wmx = 0; nlo = 0x7FFFFFFF; nhi = 0; }
    __syncthreads();

    const int qa = qlo + tid, qb = qlo + tid + TB;
    float4 pa = s_pts[dir][qa], pb = s_pts[dir][qb];
    int ca = BS[xbin(pa.x)];
    int cb = BS[xbin(pb.x)];
    atomicMin(&wmn, min(ca, cb));
    atomicMax(&wmx, max(ca, cb));

    // Needed sorted range for each query: all points with x in [x-r, x+r].
    float ba = __int_as_float(g_d[dir * NP + __float_as_int(pa.w)]);
    float bb = __int_as_float(g_d[dir * NP + __float_as_int(pb.w)]);
    float ra = sqrtf(ba) * 1.0001f;
    float rb = sqrtf(bb) * 1.0001f;
    int bloA = xbin(pa.x - ra), bhiA = xbin(pa.x + ra);
    int bloB = xbin(pb.x - rb), bhiB = xbin(pb.x + rb);
    int loA = BS[bloA];
    int loB = BS[bloB];
    int hiA = (bhiA == NB - 1) ? NP : BS[bhiA + 1];   // exclusive
    int hiB = (bhiB == NB - 1) ? NP : BS[bhiB + 1];
    atomicMin(&nlo, min(loA, loB));
    atomicMax(&nhi, max(hiA, hiB));
    __syncthreads();

    const int wlo = max(wmn - W, 0), whi = min(wmx + W, NP - 1);

    unsigned long long Qx, Qy, Qz, Qw;
    PACK2(Qx, pa.x, pb.x);
    PACK2(Qy, pa.y, pb.y);
    PACK2(Qz, pa.z, pb.z);
    PACK2(Qw, pa.x * pa.x + pa.y * pa.y + pa.z * pa.z,
              pb.x * pb.x + pb.y * pb.y + pb.z * pb.z);
    float ma = 2.0f, mb = 2.0f;

    // Extension segments: [nlo, wlo-1] and [whi+1, nhi-1] (nhi exclusive).
    {
        int lo0 = nlo, hi0 = min(wlo - 1, nhi - 1);
        if (lo0 <= hi0) scan_range(R, lo0, hi0, sh, tid, Qx, Qy, Qz, Qw, ma, mb);
    }
    __syncthreads();
    {
        int lo1 = max(whi + 1, nlo), hi1 = nhi - 1;
        if (lo1 <= hi1) scan_range(R, lo1, hi1, sh, tid, Qx, Qy, Qz, Qw, ma, mb);
    }

    atomicMin(&g_d[dir * NP + __float_as_int(pa.w)], __float_as_int(ma));
    atomicMin(&g_d[dir * NP + __float_as_int(pb.w)], __float_as_int(mb));
}

// Fixed-order deterministic sum with threshold.
__global__ void __launch_bounds__(1024) reduce_kernel(float* __restrict__ out)
{
    const int tid = threadIdx.x;
    float s = 0.0f;
#pragma unroll
    for (int k = 0; k < (2 * NP) / 1024; k++) {
        float d = __int_as_float(g_d[tid + k * 1024]);
        if (d < 2.0f) s += d;                // untouched cap 2.0 -> 0
    }
#pragma unroll
    for (int o = 16; o; o >>= 1) s += __shfl_xor_sync(0xFFFFFFFFu, s, o);

    __shared__ float ws[32];
    if ((tid & 31) == 0) ws[tid >> 5] = s;
    __syncthreads();
    if (tid < 32) {
        float v = ws[tid];
#pragma unroll
        for (int o = 16; o; o >>= 1) v += __shfl_xor_sync(0xFFFFFFFFu, v, o);
        if (tid == 0) out[0] = v * (1.0f / (float)NP);
    }
}

extern "C" void kernel_launch(void* const* d_in, const int* in_sizes, int n_in,
                              void* d_out, int out_size)
{
    const float* pc1 = (const float*)d_in[0];
    const float* pc2 = (const float*)d_in[1];
    float* out = (float*)d_out;

    build_kernel<<<1, 1024>>>(pc1, pc2);
    scatter_kernel<<<(2 * NP) / 1024, 1024>>>(pc1, pc2);
    phaseA_kernel<<<dim3(NGRP, SLICES, 2), TB>>>();
    phaseB_kernel<<<dim3(NGRP, 2), TB>>>();   // 4th launch: ncu target
    reduce_kernel<<<1, 1024>>>(out);
}

// round 16
// speedup vs baseline: 2.9950x; 2.9950x over previous
#include <cuda_runtime.h>

// Chamfer distance, pc1/pc2: (1, 16384, 3) fp32 -> scalar fp32.
// R16: sorted windowed brute (phaseA) + exact extension pass (phaseB) with
//      16-way work-proportional slicing (fixes R15's slowest-block collapse).

#define NP     16384
#define NB     4096
#define XMIN   (-6.0f)
#define XRANGE (12.0f)
#define INVBW  (NB / XRANGE)

#define QB     256                    // queries per group
#define NGRP   (NP / QB)              // 64 groups per direction
#define TB     128                    // threads (2 packed queries each)
#define W      512                    // phaseA window margin (counts)
#define SLICES 4                      // phaseA slices
#define NSLB   16                     // phaseB slices
#define CH     256                    // smem chunk points

__device__ float4 s_pts[2][NP];       // x-bin-sorted; w = original index bits
__device__ int    bin_start[2][NB];
__device__ int    scatter_pos[2][NB];
__device__ int    g_d[2 * NP];        // float bits of NN d2 (<= 2.0 cap)

#define FMA2(out, a, b, c) \
    asm("fma.rn.f32x2 %0, %1, %2, %3;" : "=l"(out) : "l"(a), "l"(b), "l"(c))
#define ADD2(out, a, b) \
    asm("add.rn.f32x2 %0, %1, %2;" : "=l"(out) : "l"(a), "l"(b))
#define PACK2(out, lo, hi) \
    asm("mov.b64 %0, {%1, %2};" : "=l"(out) : "f"(lo), "f"(hi))
#define UNPACK2(lo, hi, in) \
    asm("mov.b64 {%0, %1}, %2;" : "=f"(lo), "=f"(hi) : "l"(in))

__device__ __forceinline__ int xbin(float x) {
    int b = (int)((x - XMIN) * INVBW);
    return min(max(b, 0), NB - 1);
}

// Single block: smem histogram of both clouds + exclusive scan -> bin_start.
__global__ void __launch_bounds__(1024) build_kernel(
    const float* __restrict__ pc1, const float* __restrict__ pc2)
{
    __shared__ int sbin[2][NB];       // 32 KB
    __shared__ int wsum[32];
    const int tid = threadIdx.x, lane = tid & 31, wid = tid >> 5;

    for (int i = tid; i < 2 * NB; i += 1024) ((int*)sbin)[i] = 0;
    __syncthreads();
    for (int i = tid; i < 2 * NP; i += 1024) {
        int dir = i >> 14, idx = i & (NP - 1);
        const float* pc = dir ? pc2 : pc1;
        atomicAdd(&sbin[dir][xbin(pc[3 * idx])], 1);
    }
    __syncthreads();

#pragma unroll 1
    for (int dir = 0; dir < 2; dir++) {
        int base = tid * 4;
        int c0 = sbin[dir][base + 0], c1 = sbin[dir][base + 1];
        int c2 = sbin[dir][base + 2], c3 = sbin[dir][base + 3];
        int s0 = c0, s1 = s0 + c1, s2 = s1 + c2, s3 = s2 + c3;
        int tot = s3, v = tot;
#pragma unroll
        for (int o = 1; o < 32; o <<= 1) {
            int u = __shfl_up_sync(0xffffffffu, v, o);
            if (lane >= o) v += u;
        }
        if (lane == 31) wsum[wid] = v;
        __syncthreads();
        if (wid == 0) {
            int w = wsum[lane];
#pragma unroll
            for (int o = 1; o < 32; o <<= 1) {
                int u = __shfl_up_sync(0xffffffffu, w, o);
                if (lane >= o) w += u;
            }
            wsum[lane] = w;
        }
        __syncthreads();
        int warp_excl = (wid == 0) ? 0 : wsum[wid - 1];
        int ebase = warp_excl + (v - tot);
        bin_start[dir][base + 0] = ebase;
        bin_start[dir][base + 1] = ebase + s0;
        bin_start[dir][base + 2] = ebase + s1;
        bin_start[dir][base + 3] = ebase + s2;
        scatter_pos[dir][base + 0] = ebase;
        scatter_pos[dir][base + 1] = ebase + s0;
        scatter_pos[dir][base + 2] = ebase + s1;
        scatter_pos[dir][base + 3] = ebase + s2;
        __syncthreads();
    }
}

__global__ void scatter_kernel(const float* __restrict__ pc1,
                               const float* __restrict__ pc2) {
    int i = blockIdx.x * blockDim.x + threadIdx.x;
    int dir = i >> 14, idx = i & (NP - 1);
    const float* pc = dir ? pc2 : pc1;
    float x = pc[3 * idx], y = pc[3 * idx + 1], z = pc[3 * idx + 2];
    int pos = atomicAdd(&scatter_pos[dir][xbin(x)], 1);
    s_pts[dir][pos] = make_float4(x, y, z, __int_as_float(idx));
    g_d[i] = __float_as_int(2.0f);            // threshold cap = init
}

// Shared inner tile: scan [lo, hi] of R against 2 packed queries.
__device__ __forceinline__ void scan_range(
    const float4* __restrict__ R, int lo, int hi, float* sh, int tid,
    unsigned long long Qx, unsigned long long Qy, unsigned long long Qz,
    unsigned long long Qw, float& ma, float& mb)
{
    for (int base = lo; base <= hi; base += CH) {
        int n = min(CH, hi - base + 1);
        __syncthreads();
        for (int i = tid; i < n; i += TB) {
            float4 r = R[base + i];
            float yy = r.x * r.x + r.y * r.y + r.z * r.z;
            float* s = &sh[i * 8];
            s[0] = -2.0f * r.x; s[1] = -2.0f * r.x;
            s[2] = -2.0f * r.y; s[3] = -2.0f * r.y;
            s[4] = -2.0f * r.z; s[5] = -2.0f * r.z;
            s[6] = yy;          s[7] = yy;
        }
        __syncthreads();
#pragma unroll 4
        for (int j = 0; j < n; j++) {
            const ulonglong2* sp = (const ulonglong2*)&sh[j * 8];
            ulonglong2 A = sp[0];
            ulonglong2 B = sp[1];
            unsigned long long u1, u2, d;
            FMA2(u1, Qx, A.x, B.y);     // yy - 2 x0 y0
            FMA2(u2, Qy, A.y, Qw);      // xx - 2 x1 y1
            FMA2(u1, Qz, B.x, u1);
            ADD2(d, u1, u2);            // full d2, packed (qa, qb)
            float lo2, hi2;
            UNPACK2(lo2, hi2, d);
            ma = fminf(ma, lo2);
            mb = fminf(mb, hi2);
        }
    }
}

// Windowed brute: 256 consecutive sorted queries vs shared window, 4 slices.
__global__ void __launch_bounds__(TB) phaseA_kernel() {
    __shared__ float sh[CH * 8];
    __shared__ int wmn, wmx;
    const int tid   = threadIdx.x;
    const int qlo   = blockIdx.x * QB;
    const int slice = blockIdx.y;
    const int dir   = blockIdx.z;
    const float4* __restrict__ R = s_pts[dir ^ 1];

    if (tid == 0) { wmn = 0x7FFFFFFF; wmx = 0; }
    __syncthreads();

    const int qa = qlo + tid, qb = qlo + tid + TB;
    float4 pa = s_pts[dir][qa], pb = s_pts[dir][qb];
    int ca = bin_start[dir ^ 1][xbin(pa.x)];
    int cb = bin_start[dir ^ 1][xbin(pb.x)];
    atomicMin(&wmn, min(ca, cb));
    atomicMax(&wmx, max(ca, cb));
    __syncthreads();
    const int wlo = max(wmn - W, 0), whi = min(wmx + W, NP - 1);
    const int cnt = whi - wlo + 1;
    const int slo = wlo + (cnt * slice) / SLICES;
    const int shi = wlo + (cnt * (slice + 1)) / SLICES - 1;

    unsigned long long Qx, Qy, Qz, Qw;
    PACK2(Qx, pa.x, pb.x);
    PACK2(Qy, pa.y, pb.y);
    PACK2(Qz, pa.z, pb.z);
    PACK2(Qw, pa.x * pa.x + pa.y * pa.y + pa.z * pa.z,
              pb.x * pb.x + pb.y * pb.y + pb.z * pb.z);
    float ma = 2.0f, mb = 2.0f;

    scan_range(R, slo, shi, sh, tid, Qx, Qy, Qz, Qw, ma, mb);

    atomicMin(&g_d[dir * NP + __float_as_int(pa.w)], __float_as_int(ma));
    atomicMin(&g_d[dir * NP + __float_as_int(pb.w)], __float_as_int(mb));
}

// Exact completion, 16-way sliced: per-group extension segments are
// concatenated into a linear range; slice k scans its 1/16.
__global__ void __launch_bounds__(TB) phaseB_kernel() {
    __shared__ float sh[CH * 8];
    __shared__ int wmn, wmx, nlo, nhi;
    const int tid   = threadIdx.x;
    const int qlo   = blockIdx.x * QB;
    const int slice = blockIdx.y;
    const int dir   = blockIdx.z;
    const float4* __restrict__ R = s_pts[dir ^ 1];
    const int* __restrict__ BS = bin_start[dir ^ 1];

    if (tid == 0) { wmn = 0x7FFFFFFF; wmx = 0; nlo = 0x7FFFFFFF; nhi = 0; }
    __syncthreads();

    const int qa = qlo + tid, qb = qlo + tid + TB;
    float4 pa = s_pts[dir][qa], pb = s_pts[dir][qb];
    int ca = BS[xbin(pa.x)];
    int cb = BS[xbin(pb.x)];
    atomicMin(&wmn, min(ca, cb));
    atomicMax(&wmx, max(ca, cb));

    // Needed sorted range per query: all points with x in [x-r, x+r].
    float ba = __int_as_float(g_d[dir * NP + __float_as_int(pa.w)]);
    float bb = __int_as_float(g_d[dir * NP + __float_as_int(pb.w)]);
    float ra = sqrtf(ba) * 1.0001f;
    float rb = sqrtf(bb) * 1.0001f;
    int bloA = xbin(pa.x - ra), bhiA = xbin(pa.x + ra);
    int bloB = xbin(pb.x - rb), bhiB = xbin(pb.x + rb);
    int loA = BS[bloA];
    int loB = BS[bloB];
    int hiA = (bhiA == NB - 1) ? NP : BS[bhiA + 1];   // exclusive
    int hiB = (bhiB == NB - 1) ? NP : BS[bhiB + 1];
    atomicMin(&nlo, min(loA, loB));
    atomicMax(&nhi, max(hiA, hiB));
    __syncthreads();

    const int wlo = max(wmn - W, 0), whi = min(wmx + W, NP - 1);

    // Extension segments: seg1 = [nlo, wlo-1], seg2 = [whi+1, nhi-1].
    const int L1 = max(0, wlo - nlo);
    const int L2 = max(0, nhi - (whi + 1));
    const int L  = L1 + L2;
    const int o0 = (L * slice) / NSLB;
    const int o1 = (L * (slice + 1)) / NSLB;
    if (o0 >= o1) return;

    unsigned long long Qx, Qy, Qz, Qw;
    PACK2(Qx, pa.x, pb.x);
    PACK2(Qy, pa.y, pb.y);
    PACK2(Qz, pa.z, pb.z);
    PACK2(Qw, pa.x * pa.x + pa.y * pa.y + pa.z * pa.z,
              pb.x * pb.x + pb.y * pb.y + pb.z * pb.z);
    float ma = 2.0f, mb = 2.0f;

    // Part in seg1: linear offsets [o0, min(o1, L1))
    {
        int a = o0, b = min(o1, L1);
        if (a < b) scan_range(R, nlo + a, nlo + b - 1, sh, tid,
                              Qx, Qy, Qz, Qw, ma, mb);
    }
    __syncthreads();
    // Part in seg2: linear offsets [max(o0, L1), o1)
    {
        int a = max(o0, L1), b = o1;
        if (a < b) scan_range(R, whi + 1 + (a - L1), whi + 1 + (b - L1) - 1,
                              sh, tid, Qx, Qy, Qz, Qw, ma, mb);
    }

    atomicMin(&g_d[dir * NP + __float_as_int(pa.w)], __float_as_int(ma));
    atomicMin(&g_d[dir * NP + __float_as_int(pb.w)], __float_as_int(mb));
}

// Fixed-order deterministic sum with threshold.
__global__ void __launch_bounds__(1024) reduce_kernel(float* __restrict__ out)
{
    const int tid = threadIdx.x;
    float s = 0.0f;
#pragma unroll
    for (int k = 0; k < (2 * NP) / 1024; k++) {
        float d = __int_as_float(g_d[tid + k * 1024]);
        if (d < 2.0f) s += d;                // untouched cap 2.0 -> 0
    }
#pragma unroll
    for (int o = 16; o; o >>= 1) s += __shfl_xor_sync(0xFFFFFFFFu, s, o);

    __shared__ float ws[32];
    if ((tid & 31) == 0) ws[tid >> 5] = s;
    __syncthreads();
    if (tid < 32) {
        float v = ws[tid];
#pragma unroll
        for (int o = 16; o; o >>= 1) v += __shfl_xor_sync(0xFFFFFFFFu, v, o);
        if (tid == 0) out[0] = v * (1.0f / (float)NP);
    }
}

extern "C" void kernel_launch(void* const* d_in, const int* in_sizes, int n_in,
                              void* d_out, int out_size)
{
    const float* pc1 = (const float*)d_in[0];
    const float* pc2 = (const float*)d_in[1];
    float* out = (float*)d_out;

    build_kernel<<<1, 1024>>>(pc1, pc2);
    scatter_kernel<<<(2 * NP) / 1024, 1024>>>(pc1, pc2);
    phaseA_kernel<<<dim3(NGRP, SLICES, 2), TB>>>();
    phaseB_kernel<<<dim3(NGRP, NSLB, 2), TB>>>();   // 4th launch: ncu target
    reduce_kernel<<<1, 1024>>>(out);
}